// round 13
// baseline (speedup 1.0000x reference)
#include <cuda_runtime.h>
#include <math.h>

#define PI_F 3.14159265358979323846f
#define HPI_F 1.57079632679489662f

#define BB 8

// ---------- static scratch ----------
// L0 quad arrays, CHANNEL-MAJOR: word0 = R of 4 corners (y0x0,y0x1,y1x0,y1x1), word1 = G, word2 = B
__device__ uint4 g_q0[BB * 512 * 1024];   // 67MB
__device__ uint4 g_q1[BB * 512 * 1024];
// linear packed-RGB8 tgt mips per frame: L2@1048576 (262144), L3@1310720 (65536)  (L1 region unused)
__device__ unsigned int g_c0[1376256];
__device__ unsigned int g_c1[1376256];
// channel-major quad mips for L1 (written directly by dense): 512x256 per b
__device__ uint4 g_qm0[1048576];
__device__ uint4 g_qm1[1048576];
// ref planar fp32 L1 mip, plane pp=b*3+c: stride 131072 (512x256)
__device__ __align__(16) float g_refM[3145728];
// R|t packed rows
__device__ float4 g_Rt[BB * 2 * 3];
// sincos tables: lon sizes 1024,512,256,128 @ offs 0,1024,1536,1792
//                lat sizes 512,256,128,64  @ offs 0,512,768,896
__device__ float2 g_lonT[1920];
__device__ float2 g_latT[960];
__device__ double g_acc[4];
__device__ int g_done;

#define TOTAL_LOSS_BLOCKS (16384 + 4096 + 1280)

// ---------- fast atan poly on [0,1] ----------
__device__ __forceinline__ float atanp(float r) {
    float z = r * r;
    float p = -0.0117212f;
    p = fmaf(p, z, 0.05265332f);
    p = fmaf(p, z, -0.11643287f);
    p = fmaf(p, z, 0.19354346f);
    p = fmaf(p, z, -0.33262347f);
    p = fmaf(p, z, 0.99997726f);
    return r * p;
}

__device__ __forceinline__ void project_eq(
    float px, float py, float pz, int h, int w, float& fx, float& fy)
{
    float ax = fabsf(px), az = fabsf(pz);
    float mn = fminf(ax, az), mx = fmaxf(ax, az);
    float t = atanp(__fdividef(mn, mx));
    t = (ax > az) ? (HPI_F - t) : t;
    t = (pz < 0.0f) ? (PI_F - t) : t;
    float lo = copysignf(t, px);
    float q = py * py;
    float s2 = fmaf(px, px, pz * pz);
    float mn2 = fminf(q, s2), mx2 = fmaxf(q, s2);
    float t2 = atanp(sqrtf(__fdividef(mn2, mx2)));
    t2 = (q > s2) ? (HPI_F - t2) : t2;
    float la = copysignf(t2, py);
    fx = (lo * (1.0f / PI_F) + 1.0f) * (0.5f * (float)(w - 1));
    fy = (la * (2.0f / PI_F) + 1.0f) * (0.5f * (float)(h - 1));
    fx = fminf(fmaxf(fx, 0.0f), (float)(w - 1));
    fy = fminf(fmaxf(fy, 0.0f), (float)(h - 1));
}

__device__ __forceinline__ unsigned int q8(float a, float b, float c) {
    unsigned int r = __float2uint_rn(__saturatef(a) * 255.0f);
    unsigned int g = __float2uint_rn(__saturatef(b) * 255.0f);
    unsigned int bl = __float2uint_rn(__saturatef(c) * 255.0f);
    return r | (g << 8) | (bl << 16);
}

__device__ __forceinline__ uint4 qassemble(unsigned a, unsigned b, unsigned c, unsigned d) {
    unsigned ab_r = __byte_perm(a, b, 0x0040), cd_r = __byte_perm(c, d, 0x0040);
    unsigned ab_g = __byte_perm(a, b, 0x0051), cd_g = __byte_perm(c, d, 0x0051);
    unsigned ab_b = __byte_perm(a, b, 0x0062), cd_b = __byte_perm(c, d, 0x0062);
    return make_uint4(__byte_perm(ab_r, cd_r, 0x5410),
                      __byte_perm(ab_g, cd_g, 0x5410),
                      __byte_perm(ab_b, cd_b, 0x5410), 0u);
}

// dp4a bilinear from a prefetched channel-major quad
__device__ __forceinline__ float quad_blend(
    uint4 Q, float fx, float fy, float r0, float r1, float r2, float m)
{
    float x0f = floorf(fx), y0f = floorf(fy);
    float wx1 = fx - x0f, wy1 = fy - y0f;
    float wx0 = 1.0f - wx1, wy0 = 1.0f - wy1;
    unsigned qa = __float2uint_rn(wx0 * wy0 * 255.0f);
    unsigned qc = __float2uint_rn(wx1 * wy0 * 255.0f);
    unsigned qb = __float2uint_rn(wx0 * wy1 * 255.0f);
    int qdi = 255 - (int)(qa + qc + qb);
    unsigned qd = (unsigned)max(qdi, 0);
    unsigned wq = qa | (qc << 8) | (qb << 16) | (qd << 24);
    const float inv = 1.0f / 65025.0f;
    float w0 = (float)__dp4a(Q.x, wq, 0u) * inv;
    float w1 = (float)__dp4a(Q.y, wq, 0u) * inv;
    float w2 = (float)__dp4a(Q.z, wq, 0u) * inv;
    return m * (fabsf(r0 - w0) + fabsf(r1 - w1) + fabsf(r2 - w2));
}

// quad loaded from quad array
__device__ __forceinline__ float quad_term(
    const uint4* __restrict__ Qarr, int b, int h, int w,
    float fx, float fy, float r0, float r1, float r2, float m)
{
    int x0 = (int)floorf(fx), y0 = (int)floorf(fy);
    uint4 Q = __ldg(Qarr + (size_t)(b * h + y0) * w + x0);
    return quad_blend(Q, fx, fy, r0, r1, r2, m);
}

// quad assembled from 4 scalar gathers on packed RGB8 mip
__device__ __forceinline__ float quad_term_g(
    const unsigned* __restrict__ Carr, int b, int h, int w,
    float fx, float fy, float r0, float r1, float r2, float m)
{
    int x0 = (int)floorf(fx), y0 = (int)floorf(fy);
    int x1 = min(x0 + 1, w - 1), y1 = min(y0 + 1, h - 1);
    const unsigned* base = Carr + (size_t)b * h * w;
    unsigned c00 = __ldg(base + y0 * w + x0);
    unsigned c01 = __ldg(base + y0 * w + x1);
    unsigned c10 = __ldg(base + y1 * w + x0);
    unsigned c11 = __ldg(base + y1 * w + x1);
    uint4 Q = qassemble(c00, c01, c10, c11);
    return quad_blend(Q, fx, fy, r0, r1, r2, m);
}

__device__ __forceinline__ void loss_reduce_finalize(float acc, int accIdx, float* out) {
    #pragma unroll
    for (int o = 16; o > 0; o >>= 1) acc += __shfl_down_sync(0xffffffffu, acc, o);
    __shared__ float ws[8];
    int lane = threadIdx.x & 31, warp = threadIdx.x >> 5;
    if (lane == 0) ws[warp] = acc;
    __syncthreads();
    if (threadIdx.x == 0) {
        float s = 0.0f;
        #pragma unroll
        for (int i = 0; i < 8; i++) s += ws[i];
        atomicAdd(&g_acc[accIdx], (double)s);
        __threadfence();
        int done = atomicAdd(&g_done, 1);
        if (done == TOTAL_LOSS_BLOCKS - 1) {
            double l = g_acc[0] * (1.0 / 12582912.0)
                     + g_acc[1] * (1.0 / 3145728.0)
                     + g_acc[2] * (1.0 / 786432.0)
                     + g_acc[3] * (1.0 / 196608.0);
            out[0] = (float)l;
        }
    }
}

// ---------- DENSE: 32x32 tile; L0 quads, L1 quad mips (with halo), L2/L3 RGB8 mips ----------
__global__ __launch_bounds__(256) void bp_dense(
    const float* __restrict__ tgt0, const float* __restrict__ tgt1,
    const float* __restrict__ pose)
{
    int tid = threadIdx.x;
    int blk = blockIdx.x;            // 4096 = 32 x 16 x 8

    if (blk == 0) {
        if (tid < 4) g_acc[tid] = 0.0;
        if (tid == 4) g_done = 0;
        if (tid < BB * 2) {
            const float* p = pose + tid * 6;
            float rx = p[3], ry = p[4], rz = p[5];
            float th = sqrtf(rx * rx + ry * ry + rz * rz);
            float inv = 1.0f / fmaxf(th, 1e-8f);
            float kx = rx * inv, ky = ry * inv, kz = rz * inv;
            float s = sinf(th), c = cosf(th), ic = 1.0f - c;
            g_Rt[tid * 3 + 0] = make_float4(c + ic * kx * kx,      ic * kx * ky - s * kz, ic * kx * kz + s * ky, p[0]);
            g_Rt[tid * 3 + 1] = make_float4(ic * ky * kx + s * kz, c + ic * ky * ky,      ic * ky * kz - s * kx, p[1]);
            g_Rt[tid * 3 + 2] = make_float4(ic * kz * kx - s * ky, ic * kz * ky + s * kx, c + ic * kz * kz,      p[2]);
        }
        for (int i = tid; i < 1920; i += 256) {
            int off, w;
            if (i < 1024)      { off = 0;    w = 1024; }
            else if (i < 1536) { off = 1024; w = 512; }
            else if (i < 1792) { off = 1536; w = 256; }
            else               { off = 1792; w = 128; }
            int xi = i - off;
            float lon = ((xi + 0.5f) / (float)w * 2.0f - 1.0f) * PI_F;
            g_lonT[i] = make_float2(sinf(lon), cosf(lon));
        }
        for (int i = tid; i < 960; i += 256) {
            int off, h;
            if (i < 512)      { off = 0;   h = 512; }
            else if (i < 768) { off = 512; h = 256; }
            else if (i < 896) { off = 768; h = 128; }
            else              { off = 896; h = 64; }
            int yi = i - off;
            float lat = -((yi + 0.5f) / (float)h * 2.0f - 1.0f) * HPI_F;
            g_latT[i] = make_float2(sinf(lat), cosf(lat));
        }
    }

    int bx = blk & 31;
    int by = (blk >> 5) & 15;
    int b  = blk >> 9;
    int sx = tid & 7;
    int sy = tid >> 3;
    int x0 = bx * 32 + sx * 4;
    int y  = by * 32 + sy;

    const int hw = 512 * 1024;
    size_t base3 = (size_t)b * 3 * hw + y * 1024 + x0;

    float4 a0 = *(const float4*)(tgt0 + base3);
    float4 a1 = *(const float4*)(tgt0 + base3 + hw);
    float4 a2 = *(const float4*)(tgt0 + base3 + 2 * hw);
    float4 b0 = *(const float4*)(tgt1 + base3);
    float4 b1 = *(const float4*)(tgt1 + base3 + hw);
    float4 b2 = *(const float4*)(tgt1 + base3 + 2 * hw);

    __shared__ unsigned smA[34 * 34], smB[34 * 34];
    {
        int si = sy * 34 + sx * 4;
        smA[si + 0] = q8(a0.x, a1.x, a2.x);
        smA[si + 1] = q8(a0.y, a1.y, a2.y);
        smA[si + 2] = q8(a0.z, a1.z, a2.z);
        smA[si + 3] = q8(a0.w, a1.w, a2.w);
        smB[si + 0] = q8(b0.x, b1.x, b2.x);
        smB[si + 1] = q8(b0.y, b1.y, b2.y);
        smB[si + 2] = q8(b0.z, b1.z, b2.z);
        smB[si + 3] = q8(b0.w, b1.w, b2.w);
    }
    // halo: 2-wide right cols (rows 0..33) + 2-deep bottom rows (cols 0..31) = 132/frame
    for (int i = tid; i < 264; i += 256) {
        int f = (i >= 132);
        int j = i - f * 132;
        int lxh, lyh;
        if (j < 68) { lxh = 32 + (j & 1); lyh = j >> 1; }
        else        { int k = j - 68; lyh = 32 + (k & 1); lxh = k >> 1; }
        int gx = min(bx * 32 + lxh, 1023);
        int gy = min(by * 32 + lyh, 511);
        const float* src = f ? tgt1 : tgt0;
        size_t hb = (size_t)b * 3 * hw + gy * 1024 + gx;
        unsigned v = q8(__ldg(src + hb), __ldg(src + hb + hw), __ldg(src + hb + 2 * hw));
        (f ? smB : smA)[lyh * 34 + lxh] = v;
    }

    // ---- L1 fp32: horizontal pairs + vertical shfl_xor(8) ----
    float h0A0 = a0.x + a0.y, h1A0 = a0.z + a0.w;
    float h0A1 = a1.x + a1.y, h1A1 = a1.z + a1.w;
    float h0A2 = a2.x + a2.y, h1A2 = a2.z + a2.w;
    float h0B0 = b0.x + b0.y, h1B0 = b0.z + b0.w;
    float h0B1 = b1.x + b1.y, h1B1 = b1.z + b1.w;
    float h0B2 = b2.x + b2.y, h1B2 = b2.z + b2.w;
    #define Vred(v) v += __shfl_xor_sync(0xffffffffu, v, 8); v *= 0.25f;
    Vred(h0A0); Vred(h1A0); Vred(h0A1); Vred(h1A1); Vred(h0A2); Vred(h1A2);
    Vred(h0B0); Vred(h1B0); Vred(h0B1); Vred(h1B1); Vred(h0B2); Vred(h1B2);
    #undef Vred

    __shared__ float4 st0[256];
    __shared__ float4 st1[256];
    __shared__ float4 st0b[64];
    __shared__ float4 st1b[64];
    __shared__ unsigned smQ0[17 * 17], smQ1[17 * 17];

    if ((sy & 1) == 0) {
        int lx1 = sx * 2, ly1 = sy >> 1;
        int si = ly1 * 16 + lx1;
        st0[si]     = make_float4(h0A0, h0A1, h0A2, 0.0f);
        st0[si + 1] = make_float4(h1A0, h1A1, h1A2, 0.0f);
        st1[si]     = make_float4(h0B0, h0B1, h0B2, 0.0f);
        st1[si + 1] = make_float4(h1B0, h1B1, h1B2, 0.0f);
        int qi = ly1 * 17 + lx1;
        smQ0[qi]     = q8(h0A0, h0A1, h0A2);
        smQ0[qi + 1] = q8(h1A0, h1A1, h1A2);
        smQ1[qi]     = q8(h0B0, h0B1, h0B2);
        smQ1[qi + 1] = q8(h1B0, h1B1, h1B2);
    }
    __syncthreads();

    // ---- L0 quad assembly + write ----
    {
        int si = sy * 34 + sx * 4;
        unsigned rA0[5], rA1[5], rB0[5], rB1[5];
        #pragma unroll
        for (int i = 0; i < 5; i++) {
            rA0[i] = smA[si + i];      rA1[i] = smA[si + 34 + i];
            rB0[i] = smB[si + i];      rB1[i] = smB[si + 34 + i];
        }
        size_t go = (size_t)(b * 512 + y) * 1024 + x0;
        #pragma unroll
        for (int i = 0; i < 4; i++) {
            g_q0[go + i] = qassemble(rA0[i], rA0[i + 1], rA1[i], rA1[i + 1]);
            g_q1[go + i] = qassemble(rB0[i], rB0[i + 1], rB1[i], rB1[i + 1]);
        }
    }

    // ---- L1 u8 halo (17th row/col), clamped at L1 coords ----
    if (tid < 66) {
        int f = (tid >= 33);
        int j = tid - f * 33;
        int lx1, ly1;
        if (j < 17) { lx1 = 16; ly1 = j; }
        else        { ly1 = 16; lx1 = j - 17; }
        int gx2 = min(bx * 16 + lx1, 511);
        int gy2 = min(by * 16 + ly1, 255);
        int l0x = 2 * gx2 - bx * 32;
        int l0y = 2 * gy2 - by * 32;
        const unsigned* S = f ? smB : smA;
        unsigned w00 = S[l0y * 34 + l0x],     w01 = S[l0y * 34 + l0x + 1];
        unsigned w10 = S[(l0y + 1) * 34 + l0x], w11 = S[(l0y + 1) * 34 + l0x + 1];
        unsigned mword = 0;
        #pragma unroll
        for (int c = 0; c < 24; c += 8) {
            unsigned s = ((w00 >> c) & 255u) + ((w01 >> c) & 255u)
                       + ((w10 >> c) & 255u) + ((w11 >> c) & 255u);
            mword |= (((s + 2u) >> 2) & 255u) << c;
        }
        (f ? smQ1 : smQ0)[ly1 * 17 + lx1] = mword;
    }

    // ---- L2 (8x8 per block) ----
    if (tid < 64) {
        int lx2 = tid & 7, ly2 = tid >> 3;
        int i00 = (2 * ly2) * 16 + 2 * lx2;
        int i01 = i00 + 1, i10 = i00 + 16, i11 = i00 + 17;
        float q0x = 0.25f * (st0[i00].x + st0[i01].x + st0[i10].x + st0[i11].x);
        float q0y = 0.25f * (st0[i00].y + st0[i01].y + st0[i10].y + st0[i11].y);
        float q0z = 0.25f * (st0[i00].z + st0[i01].z + st0[i10].z + st0[i11].z);
        float q1x = 0.25f * (st1[i00].x + st1[i01].x + st1[i10].x + st1[i11].x);
        float q1y = 0.25f * (st1[i00].y + st1[i01].y + st1[i10].y + st1[i11].y);
        float q1z = 0.25f * (st1[i00].z + st1[i01].z + st1[i10].z + st1[i11].z);
        int x2g = bx * 8 + lx2, y2g = by * 8 + ly2;
        g_c0[1048576 + (b * 128 + y2g) * 256 + x2g] = q8(q0x, q0y, q0z);
        g_c1[1048576 + (b * 128 + y2g) * 256 + x2g] = q8(q1x, q1y, q1z);
        int si = ly2 * 8 + lx2;
        st0b[si] = make_float4(q0x, q0y, q0z, 0.0f);
        st1b[si] = make_float4(q1x, q1y, q1z, 0.0f);
    }
    __syncthreads();

    // ---- L1 quad-mip assembly (256 quads, one per thread per frame) ----
    {
        int lx = tid & 15, ly = tid >> 4;
        int qi = ly * 17 + lx;
        int x2g = bx * 16 + lx, y2g = by * 16 + ly;
        size_t go = (size_t)(b * 256 + y2g) * 512 + x2g;
        g_qm0[go] = qassemble(smQ0[qi], smQ0[qi + 1], smQ0[qi + 17], smQ0[qi + 18]);
        g_qm1[go] = qassemble(smQ1[qi], smQ1[qi + 1], smQ1[qi + 17], smQ1[qi + 18]);
    }

    // ---- L3 (4x4 per block) ----
    if (tid < 16) {
        int lx3 = tid & 3, ly3 = tid >> 2;
        int i00 = (2 * ly3) * 8 + 2 * lx3;
        int i01 = i00 + 1, i10 = i00 + 8, i11 = i00 + 9;
        float q0x = 0.25f * (st0b[i00].x + st0b[i01].x + st0b[i10].x + st0b[i11].x);
        float q0y = 0.25f * (st0b[i00].y + st0b[i01].y + st0b[i10].y + st0b[i11].y);
        float q0z = 0.25f * (st0b[i00].z + st0b[i01].z + st0b[i10].z + st0b[i11].z);
        float q1x = 0.25f * (st1b[i00].x + st1b[i01].x + st1b[i10].x + st1b[i11].x);
        float q1y = 0.25f * (st1b[i00].y + st1b[i01].y + st1b[i10].y + st1b[i11].y);
        float q1z = 0.25f * (st1b[i00].z + st1b[i01].z + st1b[i10].z + st1b[i11].z);
        int x3g = bx * 4 + lx3, y3g = by * 4 + ly3;
        g_c0[1310720 + (b * 64 + y3g) * 128 + x3g] = q8(q0x, q0y, q0z);
        g_c1[1310720 + (b * 64 + y3g) * 128 + x3g] = q8(q1x, q1y, q1z);
    }
}

// ---------- merged loss: L0 (+ refL1) for blocks < 16384, L1 level for blocks >= 16384 ----------
__global__ __launch_bounds__(256) void bp_loss(
    const float* __restrict__ ref, const float* __restrict__ depth0,
    const float* __restrict__ mask0, const float* __restrict__ depth1,
    const float* __restrict__ mask1, float* __restrict__ out)
{
    int tid = threadIdx.x;
    int blk = blockIdx.x;
    const int hw0 = 512 * 1024;

    if (blk >= 16384) {
        // ---- loss level 1 (depends only on dense's g_qm) ----
        int idx = (blk - 16384) * 256 + tid;      // [0, 1048576)
        int x = idx & 511, y = (idx >> 9) & 255, b = idx >> 17;
        // ref inline from ref_rgb
        float rr[3];
        size_t rbase = (size_t)b * 3 * hw0 + (2 * y) * 1024 + 2 * x;
        #pragma unroll
        for (int c = 0; c < 3; c++) {
            float2 u0 = *(const float2*)(ref + rbase + (size_t)c * hw0);
            float2 u1 = *(const float2*)(ref + rbase + (size_t)c * hw0 + 1024);
            rr[c] = 0.25f * ((u0.x + u0.y) + (u1.x + u1.y));
        }
        float2 lc = g_lonT[1024 + x];
        float2 lt = g_latT[512 + y];
        float d = __ldg(depth1 + idx);
        float xx = d * lt.y * lc.x;
        float yy = d * lt.x;
        float zz = d * lt.y * lc.y;
        int p = y * 512 + x;
        float acc = 0.0f;
        #pragma unroll
        for (int n = 0; n < 2; n++) {
            const float4* Rt = g_Rt + (b * 2 + n) * 3;
            float4 A = __ldg(Rt), B = __ldg(Rt + 1), C = __ldg(Rt + 2);
            float px = A.x * xx + A.y * yy + A.z * zz + A.w;
            float py = B.x * xx + B.y * yy + B.z * zz + B.w;
            float pz = C.x * xx + C.y * yy + C.z * zz + C.w;
            float fx, fy;
            project_eq(px, py, pz, 256, 512, fx, fy);
            float m = __ldg(mask1 + (size_t)(b * 2 + n) * 131072 + p);
            acc += quad_term(n ? g_qm1 : g_qm0, b, 256, 512, fx, fy, rr[0], rr[1], rr[2], m);
        }
        loss_reduce_finalize(acc, 1, out);
        return;
    }

    int lane = tid & 31, wid = tid >> 5;
    int bx = blk & 63;
    int by = (blk >> 6) & 31;
    int b  = blk >> 11;
    int tx = lane & 15;
    int sub = lane >> 4;
    int x = bx * 16 + tx;
    int y = by * 16 + wid * 2 + sub;

    int p = y * 1024 + x;
    size_t base3 = (size_t)b * 3 * hw0 + p;
    float r0 = __ldg(ref + base3), r1 = __ldg(ref + base3 + hw0), r2 = __ldg(ref + base3 + 2 * hw0);
    float d  = __ldg(depth0 + (size_t)b * hw0 + p);
    float m0 = __ldg(mask0 + (size_t)(b * 2) * hw0 + p);
    float m1 = __ldg(mask0 + (size_t)(b * 2 + 1) * hw0 + p);

    // ---- ref L1 via shfl (no syncs) — consumed by bp_loss23 ----
    #define RED4(v) { v += __shfl_xor_sync(0xffffffffu, v, 1); v += __shfl_xor_sync(0xffffffffu, v, 16); v *= 0.25f; }
    float a0 = r0, a1 = r1, a2 = r2;
    RED4(a0); RED4(a1); RED4(a2);
    #undef RED4
    if (sub == 0 && (tx & 1) == 0) {
        int x2 = x >> 1, y2 = y >> 1;
        size_t ro = (size_t)(b * 3) * 131072 + y2 * 512 + x2;
        g_refM[ro] = a0; g_refM[ro + 131072] = a1; g_refM[ro + 262144] = a2;
    }

    float2 lc = g_lonT[x];
    float2 lt = g_latT[y];
    float xx = d * lt.y * lc.x;
    float yy = d * lt.x;
    float zz = d * lt.y * lc.y;
    float acc = 0.0f;
    #pragma unroll
    for (int n = 0; n < 2; n++) {
        const float4* Rt = g_Rt + (b * 2 + n) * 3;
        float4 A = __ldg(Rt), B = __ldg(Rt + 1), C = __ldg(Rt + 2);
        float px = A.x * xx + A.y * yy + A.z * zz + A.w;
        float py = B.x * xx + B.y * yy + B.z * zz + B.w;
        float pz = C.x * xx + C.y * yy + C.z * zz + C.w;
        float fx, fy;
        project_eq(px, py, pz, 512, 1024, fx, fy);
        acc += quad_term(n ? g_q1 : g_q0, b, 512, 1024, fx, fy, r0, r1, r2, n ? m1 : m0);
    }
    loss_reduce_finalize(acc, 0, out);
}

// ---------- tail: loss levels 2..3 (ref from refL1; gathers assemble quads from g_c) ----------
__global__ __launch_bounds__(256) void bp_loss23(
    const float* __restrict__ d2, const float* __restrict__ m2,
    const float* __restrict__ d3, const float* __restrict__ m3,
    float* __restrict__ out)
{
    int blk = blockIdx.x;
    const float *dep, *msk;
    int h, w, lw, lh, lonO, latO, accI, base, coff;
    if (blk < 1024) { dep = d2; msk = m2; h = 128; w = 256; lw = 8; lh = 7; lonO = 1536; latO = 768; coff = 1048576; accI = 2; base = 0; }
    else            { dep = d3; msk = m3; h = 64;  w = 128; lw = 7; lh = 6; lonO = 1792; latO = 896; coff = 1310720; accI = 3; base = 1024; }
    int idx = (blk - base) * 256 + threadIdx.x;
    int x = idx & (w - 1), y = (idx >> lw) & (h - 1), b = idx >> (lw + lh);

    // ref from fp32 refL1
    float r0, r1, r2;
    {
        size_t pb = (size_t)(b * 3) * 131072;
        if (accI == 2) {
            size_t ro = pb + (2 * y) * 512 + 2 * x;
            float rr[3];
            #pragma unroll
            for (int c = 0; c < 3; c++) {
                float2 u0 = *(const float2*)(g_refM + ro + (size_t)c * 131072);
                float2 u1 = *(const float2*)(g_refM + ro + (size_t)c * 131072 + 512);
                rr[c] = 0.25f * ((u0.x + u0.y) + (u1.x + u1.y));
            }
            r0 = rr[0]; r1 = rr[1]; r2 = rr[2];
        } else {
            size_t ro = pb + (4 * y) * 512 + 4 * x;
            float rr[3];
            #pragma unroll
            for (int c = 0; c < 3; c++) {
                float s = 0.0f;
                #pragma unroll
                for (int rrow = 0; rrow < 4; rrow++) {
                    float4 u = *(const float4*)(g_refM + ro + (size_t)c * 131072 + rrow * 512);
                    s += u.x + u.y + u.z + u.w;
                }
                rr[c] = 0.0625f * s;
            }
            r0 = rr[0]; r1 = rr[1]; r2 = rr[2];
        }
    }

    float2 lc = g_lonT[lonO + x];
    float2 lt = g_latT[latO + y];
    float d = __ldg(dep + idx);
    float xx = d * lt.y * lc.x;
    float yy = d * lt.x;
    float zz = d * lt.y * lc.y;
    int hw = h * w;
    int p = y * w + x;
    float acc = 0.0f;
    #pragma unroll
    for (int n = 0; n < 2; n++) {
        const float4* Rt = g_Rt + (b * 2 + n) * 3;
        float4 A = __ldg(Rt), B = __ldg(Rt + 1), C = __ldg(Rt + 2);
        float px = A.x * xx + A.y * yy + A.z * zz + A.w;
        float py = B.x * xx + B.y * yy + B.z * zz + B.w;
        float pz = C.x * xx + C.y * yy + C.z * zz + C.w;
        float fx, fy;
        project_eq(px, py, pz, h, w, fx, fy);
        float m = __ldg(msk + (size_t)(b * 2 + n) * hw + p);
        acc += quad_term_g((n ? g_c1 : g_c0) + coff, b, h, w, fx, fy, r0, r1, r2, m);
    }
    loss_reduce_finalize(acc, accI, out);
}

extern "C" void kernel_launch(void* const* d_in, const int* in_sizes, int n_in,
                              void* d_out, int out_size) {
    const float* depth[4];
    const float* mask[4];
    if (in_sizes[2] == 8388608) {
        for (int i = 0; i < 4; i++) {
            depth[i] = (const float*)d_in[1 + 2 * i];
            mask[i]  = (const float*)d_in[2 + 2 * i];
        }
    } else {
        for (int i = 0; i < 4; i++) {
            depth[i] = (const float*)d_in[1 + i];
            mask[i]  = (const float*)d_in[5 + i];
        }
    }
    const float* ref_rgb = (const float*)d_in[0];
    const float* tgt0 = (const float*)d_in[9];
    const float* tgt1 = (const float*)d_in[10];
    const float* pose = (const float*)d_in[11];
    float* out = (float*)d_out;

    bp_dense<<<4096, 256>>>(tgt0, tgt1, pose);
    bp_loss<<<16384 + 4096, 256>>>(ref_rgb, depth[0], mask[0], depth[1], mask[1], out);
    bp_loss23<<<1280, 256>>>(depth[2], mask[2], depth[3], mask[3], out);
    (void)n_in; (void)out_size;
}

// round 14
// speedup vs baseline: 1.0458x; 1.0458x over previous
#include <cuda_runtime.h>
#include <math.h>

#define PI_F 3.14159265358979323846f
#define HPI_F 1.57079632679489662f

#define BB 8

// ---------- static scratch ----------
__device__ uint4 g_q0[BB * 512 * 1024];   // L0 quads, channel-major
__device__ uint4 g_q1[BB * 512 * 1024];
// packed-RGB8 tgt mips per frame: L2@1048576 (32768/b), L3@1310720 (8192/b)
__device__ unsigned int g_c0[1376256];
__device__ unsigned int g_c1[1376256];
// channel-major quad mips for L1: 512x256 per b
__device__ uint4 g_qm0[1048576];
__device__ uint4 g_qm1[1048576];
// ref planar fp32 L1 mip, plane pp=b*3+c: stride 131072 (512x256)
__device__ __align__(16) float g_refM[3145728];
__device__ float4 g_Rt[BB * 2 * 3];
__device__ float2 g_lonT[1920];
__device__ float2 g_latT[960];
__device__ double g_acc[4];
__device__ int g_done;

#define TOTAL_LOSS_BLOCKS (16384 + 4096 + 1280)

__device__ __forceinline__ float atanp(float r) {
    float z = r * r;
    float p = -0.0117212f;
    p = fmaf(p, z, 0.05265332f);
    p = fmaf(p, z, -0.11643287f);
    p = fmaf(p, z, 0.19354346f);
    p = fmaf(p, z, -0.33262347f);
    p = fmaf(p, z, 0.99997726f);
    return r * p;
}

__device__ __forceinline__ void project_eq(
    float px, float py, float pz, int h, int w, float& fx, float& fy)
{
    float ax = fabsf(px), az = fabsf(pz);
    float mn = fminf(ax, az), mx = fmaxf(ax, az);
    float t = atanp(__fdividef(mn, mx));
    t = (ax > az) ? (HPI_F - t) : t;
    t = (pz < 0.0f) ? (PI_F - t) : t;
    float lo = copysignf(t, px);
    float q = py * py;
    float s2 = fmaf(px, px, pz * pz);
    float mn2 = fminf(q, s2), mx2 = fmaxf(q, s2);
    float t2 = atanp(sqrtf(__fdividef(mn2, mx2)));
    t2 = (q > s2) ? (HPI_F - t2) : t2;
    float la = copysignf(t2, py);
    fx = (lo * (1.0f / PI_F) + 1.0f) * (0.5f * (float)(w - 1));
    fy = (la * (2.0f / PI_F) + 1.0f) * (0.5f * (float)(h - 1));
    fx = fminf(fmaxf(fx, 0.0f), (float)(w - 1));
    fy = fminf(fmaxf(fy, 0.0f), (float)(h - 1));
}

__device__ __forceinline__ unsigned int q8(float a, float b, float c) {
    unsigned int r = __float2uint_rn(__saturatef(a) * 255.0f);
    unsigned int g = __float2uint_rn(__saturatef(b) * 255.0f);
    unsigned int bl = __float2uint_rn(__saturatef(c) * 255.0f);
    return r | (g << 8) | (bl << 16);
}

__device__ __forceinline__ uint4 qassemble(unsigned a, unsigned b, unsigned c, unsigned d) {
    unsigned ab_r = __byte_perm(a, b, 0x0040), cd_r = __byte_perm(c, d, 0x0040);
    unsigned ab_g = __byte_perm(a, b, 0x0051), cd_g = __byte_perm(c, d, 0x0051);
    unsigned ab_b = __byte_perm(a, b, 0x0062), cd_b = __byte_perm(c, d, 0x0062);
    return make_uint4(__byte_perm(ab_r, cd_r, 0x5410),
                      __byte_perm(ab_g, cd_g, 0x5410),
                      __byte_perm(ab_b, cd_b, 0x5410), 0u);
}

__device__ __forceinline__ float quad_blend(
    uint4 Q, float fx, float fy, float r0, float r1, float r2, float m)
{
    float x0f = floorf(fx), y0f = floorf(fy);
    float wx1 = fx - x0f, wy1 = fy - y0f;
    float wx0 = 1.0f - wx1, wy0 = 1.0f - wy1;
    unsigned qa = __float2uint_rn(wx0 * wy0 * 255.0f);
    unsigned qc = __float2uint_rn(wx1 * wy0 * 255.0f);
    unsigned qb = __float2uint_rn(wx0 * wy1 * 255.0f);
    int qdi = 255 - (int)(qa + qc + qb);
    unsigned qd = (unsigned)max(qdi, 0);
    unsigned wq = qa | (qc << 8) | (qb << 16) | (qd << 24);
    const float inv = 1.0f / 65025.0f;
    float w0 = (float)__dp4a(Q.x, wq, 0u) * inv;
    float w1 = (float)__dp4a(Q.y, wq, 0u) * inv;
    float w2 = (float)__dp4a(Q.z, wq, 0u) * inv;
    return m * (fabsf(r0 - w0) + fabsf(r1 - w1) + fabsf(r2 - w2));
}

// dual-frame term: project both, load both, blend both (2x gather MLP)
__device__ __forceinline__ float dual_term(
    const uint4* __restrict__ Q0arr, const uint4* __restrict__ Q1arr,
    int b, int h, int w,
    float xx, float yy, float zz,
    float r0, float r1, float r2, float m0, float m1)
{
    const float4* Rt0 = g_Rt + (b * 2) * 3;
    float4 A0 = __ldg(Rt0), B0 = __ldg(Rt0 + 1), C0 = __ldg(Rt0 + 2);
    float4 A1 = __ldg(Rt0 + 3), B1 = __ldg(Rt0 + 4), C1 = __ldg(Rt0 + 5);
    float px0 = A0.x * xx + A0.y * yy + A0.z * zz + A0.w;
    float py0 = B0.x * xx + B0.y * yy + B0.z * zz + B0.w;
    float pz0 = C0.x * xx + C0.y * yy + C0.z * zz + C0.w;
    float px1 = A1.x * xx + A1.y * yy + A1.z * zz + A1.w;
    float py1 = B1.x * xx + B1.y * yy + B1.z * zz + B1.w;
    float pz1 = C1.x * xx + C1.y * yy + C1.z * zz + C1.w;
    float fx0, fy0, fx1, fy1;
    project_eq(px0, py0, pz0, h, w, fx0, fy0);
    project_eq(px1, py1, pz1, h, w, fx1, fy1);
    int x00 = (int)floorf(fx0), y00 = (int)floorf(fy0);
    int x01 = (int)floorf(fx1), y01 = (int)floorf(fy1);
    uint4 Q0 = __ldg(Q0arr + (size_t)(b * h + y00) * w + x00);
    uint4 Q1 = __ldg(Q1arr + (size_t)(b * h + y01) * w + x01);
    return quad_blend(Q0, fx0, fy0, r0, r1, r2, m0)
         + quad_blend(Q1, fx1, fy1, r0, r1, r2, m1);
}

// dual-frame term for small levels (assemble quads from RGB8 mip)
__device__ __forceinline__ float dual_term_g(
    const unsigned* __restrict__ C0arr, const unsigned* __restrict__ C1arr,
    int b, int h, int w,
    float xx, float yy, float zz,
    float r0, float r1, float r2, float m0, float m1)
{
    const float4* Rt0 = g_Rt + (b * 2) * 3;
    float4 A0 = __ldg(Rt0), B0 = __ldg(Rt0 + 1), C0 = __ldg(Rt0 + 2);
    float4 A1 = __ldg(Rt0 + 3), B1 = __ldg(Rt0 + 4), C1 = __ldg(Rt0 + 5);
    float px0 = A0.x * xx + A0.y * yy + A0.z * zz + A0.w;
    float py0 = B0.x * xx + B0.y * yy + B0.z * zz + B0.w;
    float pz0 = C0.x * xx + C0.y * yy + C0.z * zz + C0.w;
    float px1 = A1.x * xx + A1.y * yy + A1.z * zz + A1.w;
    float py1 = B1.x * xx + B1.y * yy + B1.z * zz + B1.w;
    float pz1 = C1.x * xx + C1.y * yy + C1.z * zz + C1.w;
    float fx0, fy0, fx1, fy1;
    project_eq(px0, py0, pz0, h, w, fx0, fy0);
    project_eq(px1, py1, pz1, h, w, fx1, fy1);
    int xa = (int)floorf(fx0), ya = (int)floorf(fy0);
    int xb = (int)floorf(fx1), yb = (int)floorf(fy1);
    int xa1 = min(xa + 1, w - 1), ya1 = min(ya + 1, h - 1);
    int xb1 = min(xb + 1, w - 1), yb1 = min(yb + 1, h - 1);
    const unsigned* b0 = C0arr + (size_t)b * h * w;
    const unsigned* b1 = C1arr + (size_t)b * h * w;
    unsigned c00a = __ldg(b0 + ya * w + xa),  c01a = __ldg(b0 + ya * w + xa1);
    unsigned c10a = __ldg(b0 + ya1 * w + xa), c11a = __ldg(b0 + ya1 * w + xa1);
    unsigned c00b = __ldg(b1 + yb * w + xb),  c01b = __ldg(b1 + yb * w + xb1);
    unsigned c10b = __ldg(b1 + yb1 * w + xb), c11b = __ldg(b1 + yb1 * w + xb1);
    uint4 Qa = qassemble(c00a, c01a, c10a, c11a);
    uint4 Qb = qassemble(c00b, c01b, c10b, c11b);
    return quad_blend(Qa, fx0, fy0, r0, r1, r2, m0)
         + quad_blend(Qb, fx1, fy1, r0, r1, r2, m1);
}

__device__ __forceinline__ void loss_reduce_finalize(float acc, int accIdx, float* out) {
    #pragma unroll
    for (int o = 16; o > 0; o >>= 1) acc += __shfl_down_sync(0xffffffffu, acc, o);
    __shared__ float ws[8];
    int lane = threadIdx.x & 31, warp = threadIdx.x >> 5;
    if (lane == 0) ws[warp] = acc;
    __syncthreads();
    if (threadIdx.x == 0) {
        float s = 0.0f;
        #pragma unroll
        for (int i = 0; i < 8; i++) s += ws[i];
        atomicAdd(&g_acc[accIdx], (double)s);
        __threadfence();
        int done = atomicAdd(&g_done, 1);
        if (done == TOTAL_LOSS_BLOCKS - 1) {
            double l = g_acc[0] * (1.0 / 12582912.0)
                     + g_acc[1] * (1.0 / 3145728.0)
                     + g_acc[2] * (1.0 / 786432.0)
                     + g_acc[3] * (1.0 / 196608.0);
            out[0] = (float)l;
        }
    }
}

// ---------- DENSE: 32x32 tile; L0 quads, L1 quad mips, L2/L3 RGB8 mips ----------
__global__ __launch_bounds__(256) void bp_dense(
    const float* __restrict__ tgt0, const float* __restrict__ tgt1,
    const float* __restrict__ pose)
{
    int tid = threadIdx.x;
    int blk = blockIdx.x;            // 4096 = 32 x 16 x 8

    if (blk == 0) {
        if (tid < 4) g_acc[tid] = 0.0;
        if (tid == 4) g_done = 0;
        if (tid < BB * 2) {
            const float* p = pose + tid * 6;
            float rx = p[3], ry = p[4], rz = p[5];
            float th = sqrtf(rx * rx + ry * ry + rz * rz);
            float inv = 1.0f / fmaxf(th, 1e-8f);
            float kx = rx * inv, ky = ry * inv, kz = rz * inv;
            float s = sinf(th), c = cosf(th), ic = 1.0f - c;
            g_Rt[tid * 3 + 0] = make_float4(c + ic * kx * kx,      ic * kx * ky - s * kz, ic * kx * kz + s * ky, p[0]);
            g_Rt[tid * 3 + 1] = make_float4(ic * ky * kx + s * kz, c + ic * ky * ky,      ic * ky * kz - s * kx, p[1]);
            g_Rt[tid * 3 + 2] = make_float4(ic * kz * kx - s * ky, ic * kz * ky + s * kx, c + ic * kz * kz,      p[2]);
        }
        for (int i = tid; i < 1920; i += 256) {
            int off, w;
            if (i < 1024)      { off = 0;    w = 1024; }
            else if (i < 1536) { off = 1024; w = 512; }
            else if (i < 1792) { off = 1536; w = 256; }
            else               { off = 1792; w = 128; }
            int xi = i - off;
            float lon = ((xi + 0.5f) / (float)w * 2.0f - 1.0f) * PI_F;
            g_lonT[i] = make_float2(sinf(lon), cosf(lon));
        }
        for (int i = tid; i < 960; i += 256) {
            int off, h;
            if (i < 512)      { off = 0;   h = 512; }
            else if (i < 768) { off = 512; h = 256; }
            else if (i < 896) { off = 768; h = 128; }
            else              { off = 896; h = 64; }
            int yi = i - off;
            float lat = -((yi + 0.5f) / (float)h * 2.0f - 1.0f) * HPI_F;
            g_latT[i] = make_float2(sinf(lat), cosf(lat));
        }
    }

    int bx = blk & 31;
    int by = (blk >> 5) & 15;
    int b  = blk >> 9;
    int sx = tid & 7;
    int sy = tid >> 3;
    int x0 = bx * 32 + sx * 4;
    int y  = by * 32 + sy;

    const int hw = 512 * 1024;
    size_t base3 = (size_t)b * 3 * hw + y * 1024 + x0;

    float4 a0 = *(const float4*)(tgt0 + base3);
    float4 a1 = *(const float4*)(tgt0 + base3 + hw);
    float4 a2 = *(const float4*)(tgt0 + base3 + 2 * hw);
    float4 b0 = *(const float4*)(tgt1 + base3);
    float4 b1 = *(const float4*)(tgt1 + base3 + hw);
    float4 b2 = *(const float4*)(tgt1 + base3 + 2 * hw);

    unsigned wA0 = q8(a0.x, a1.x, a2.x), wA1 = q8(a0.y, a1.y, a2.y);
    unsigned wA2 = q8(a0.z, a1.z, a2.z), wA3 = q8(a0.w, a1.w, a2.w);
    unsigned wB0 = q8(b0.x, b1.x, b2.x), wB1 = q8(b0.y, b1.y, b2.y);
    unsigned wB2 = q8(b0.z, b1.z, b2.z), wB3 = q8(b0.w, b1.w, b2.w);

    __shared__ unsigned smA[34 * 34], smB[34 * 34];
    {
        int si = sy * 34 + sx * 4;
        smA[si + 0] = wA0; smA[si + 1] = wA1; smA[si + 2] = wA2; smA[si + 3] = wA3;
        smB[si + 0] = wB0; smB[si + 1] = wB1; smB[si + 2] = wB2; smB[si + 3] = wB3;
    }
    for (int i = tid; i < 264; i += 256) {
        int f = (i >= 132);
        int j = i - f * 132;
        int lxh, lyh;
        if (j < 68) { lxh = 32 + (j & 1); lyh = j >> 1; }
        else        { int k = j - 68; lyh = 32 + (k & 1); lxh = k >> 1; }
        int gx = min(bx * 32 + lxh, 1023);
        int gy = min(by * 32 + lyh, 511);
        const float* src = f ? tgt1 : tgt0;
        size_t hb = (size_t)b * 3 * hw + gy * 1024 + gx;
        unsigned v = q8(__ldg(src + hb), __ldg(src + hb + hw), __ldg(src + hb + 2 * hw));
        (f ? smB : smA)[lyh * 34 + lxh] = v;
    }

    // ---- L1 fp32: horizontal pairs + vertical shfl_xor(8) ----
    float h0A0 = a0.x + a0.y, h1A0 = a0.z + a0.w;
    float h0A1 = a1.x + a1.y, h1A1 = a1.z + a1.w;
    float h0A2 = a2.x + a2.y, h1A2 = a2.z + a2.w;
    float h0B0 = b0.x + b0.y, h1B0 = b0.z + b0.w;
    float h0B1 = b1.x + b1.y, h1B1 = b1.z + b1.w;
    float h0B2 = b2.x + b2.y, h1B2 = b2.z + b2.w;
    #define Vred(v) v += __shfl_xor_sync(0xffffffffu, v, 8); v *= 0.25f;
    Vred(h0A0); Vred(h1A0); Vred(h0A1); Vred(h1A1); Vred(h0A2); Vred(h1A2);
    Vred(h0B0); Vred(h1B0); Vred(h0B1); Vred(h1B1); Vred(h0B2); Vred(h1B2);
    #undef Vred

    __shared__ float4 st0[256];
    __shared__ float4 st1[256];
    __shared__ float4 st0b[64];
    __shared__ float4 st1b[64];
    __shared__ unsigned smQ0[17 * 17], smQ1[17 * 17];

    if ((sy & 1) == 0) {
        int lx1 = sx * 2, ly1 = sy >> 1;
        int si = ly1 * 16 + lx1;
        st0[si]     = make_float4(h0A0, h0A1, h0A2, 0.0f);
        st0[si + 1] = make_float4(h1A0, h1A1, h1A2, 0.0f);
        st1[si]     = make_float4(h0B0, h0B1, h0B2, 0.0f);
        st1[si + 1] = make_float4(h1B0, h1B1, h1B2, 0.0f);
        int qi = ly1 * 17 + lx1;
        smQ0[qi]     = q8(h0A0, h0A1, h0A2);
        smQ0[qi + 1] = q8(h1A0, h1A1, h1A2);
        smQ1[qi]     = q8(h0B0, h0B1, h0B2);
        smQ1[qi + 1] = q8(h1B0, h1B1, h1B2);
    }
    __syncthreads();

    // ---- L0 quad assembly: own words from registers, neighbor + next row from smem ----
    {
        int si = sy * 34 + sx * 4;
        unsigned rA0[5] = {wA0, wA1, wA2, wA3, smA[si + 4]};
        unsigned rB0[5] = {wB0, wB1, wB2, wB3, smB[si + 4]};
        unsigned rA1[5], rB1[5];
        #pragma unroll
        for (int i = 0; i < 5; i++) {
            rA1[i] = smA[si + 34 + i];
            rB1[i] = smB[si + 34 + i];
        }
        size_t go = (size_t)(b * 512 + y) * 1024 + x0;
        #pragma unroll
        for (int i = 0; i < 4; i++) {
            g_q0[go + i] = qassemble(rA0[i], rA0[i + 1], rA1[i], rA1[i + 1]);
            g_q1[go + i] = qassemble(rB0[i], rB0[i + 1], rB1[i], rB1[i + 1]);
        }
    }

    // ---- L1 u8 halo (17th row/col), clamped at L1 coords ----
    if (tid < 66) {
        int f = (tid >= 33);
        int j = tid - f * 33;
        int lx1, ly1;
        if (j < 17) { lx1 = 16; ly1 = j; }
        else        { ly1 = 16; lx1 = j - 17; }
        int gx2 = min(bx * 16 + lx1, 511);
        int gy2 = min(by * 16 + ly1, 255);
        int l0x = 2 * gx2 - bx * 32;
        int l0y = 2 * gy2 - by * 32;
        const unsigned* S = f ? smB : smA;
        unsigned w00 = S[l0y * 34 + l0x],       w01 = S[l0y * 34 + l0x + 1];
        unsigned w10 = S[(l0y + 1) * 34 + l0x], w11 = S[(l0y + 1) * 34 + l0x + 1];
        unsigned mword = 0;
        #pragma unroll
        for (int c = 0; c < 24; c += 8) {
            unsigned s = ((w00 >> c) & 255u) + ((w01 >> c) & 255u)
                       + ((w10 >> c) & 255u) + ((w11 >> c) & 255u);
            mword |= (((s + 2u) >> 2) & 255u) << c;
        }
        (f ? smQ1 : smQ0)[ly1 * 17 + lx1] = mword;
    }

    // ---- L2 (8x8 per block) ----
    if (tid < 64) {
        int lx2 = tid & 7, ly2 = tid >> 3;
        int i00 = (2 * ly2) * 16 + 2 * lx2;
        int i01 = i00 + 1, i10 = i00 + 16, i11 = i00 + 17;
        float q0x = 0.25f * (st0[i00].x + st0[i01].x + st0[i10].x + st0[i11].x);
        float q0y = 0.25f * (st0[i00].y + st0[i01].y + st0[i10].y + st0[i11].y);
        float q0z = 0.25f * (st0[i00].z + st0[i01].z + st0[i10].z + st0[i11].z);
        float q1x = 0.25f * (st1[i00].x + st1[i01].x + st1[i10].x + st1[i11].x);
        float q1y = 0.25f * (st1[i00].y + st1[i01].y + st1[i10].y + st1[i11].y);
        float q1z = 0.25f * (st1[i00].z + st1[i01].z + st1[i10].z + st1[i11].z);
        int x2g = bx * 8 + lx2, y2g = by * 8 + ly2;
        g_c0[1048576 + (b * 128 + y2g) * 256 + x2g] = q8(q0x, q0y, q0z);
        g_c1[1048576 + (b * 128 + y2g) * 256 + x2g] = q8(q1x, q1y, q1z);
        int si = ly2 * 8 + lx2;
        st0b[si] = make_float4(q0x, q0y, q0z, 0.0f);
        st1b[si] = make_float4(q1x, q1y, q1z, 0.0f);
    }
    __syncthreads();

    // ---- L1 quad-mip assembly ----
    {
        int lx = tid & 15, ly = tid >> 4;
        int qi = ly * 17 + lx;
        int x2g = bx * 16 + lx, y2g = by * 16 + ly;
        size_t go = (size_t)(b * 256 + y2g) * 512 + x2g;
        g_qm0[go] = qassemble(smQ0[qi], smQ0[qi + 1], smQ0[qi + 17], smQ0[qi + 18]);
        g_qm1[go] = qassemble(smQ1[qi], smQ1[qi + 1], smQ1[qi + 17], smQ1[qi + 18]);
    }

    // ---- L3 (4x4 per block) ----
    if (tid < 16) {
        int lx3 = tid & 3, ly3 = tid >> 2;
        int i00 = (2 * ly3) * 8 + 2 * lx3;
        int i01 = i00 + 1, i10 = i00 + 8, i11 = i00 + 9;
        float q0x = 0.25f * (st0b[i00].x + st0b[i01].x + st0b[i10].x + st0b[i11].x);
        float q0y = 0.25f * (st0b[i00].y + st0b[i01].y + st0b[i10].y + st0b[i11].y);
        float q0z = 0.25f * (st0b[i00].z + st0b[i01].z + st0b[i10].z + st0b[i11].z);
        float q1x = 0.25f * (st1b[i00].x + st1b[i01].x + st1b[i10].x + st1b[i11].x);
        float q1y = 0.25f * (st1b[i00].y + st1b[i01].y + st1b[i10].y + st1b[i11].y);
        float q1z = 0.25f * (st1b[i00].z + st1b[i01].z + st1b[i10].z + st1b[i11].z);
        int x3g = bx * 4 + lx3, y3g = by * 4 + ly3;
        g_c0[1310720 + (b * 64 + y3g) * 128 + x3g] = q8(q0x, q0y, q0z);
        g_c1[1310720 + (b * 64 + y3g) * 128 + x3g] = q8(q1x, q1y, q1z);
    }
}

// ---------- merged loss: L0 (+ refL1) blocks < 16384, L1 level blocks >= 16384 ----------
__global__ __launch_bounds__(256) void bp_loss(
    const float* __restrict__ ref, const float* __restrict__ depth0,
    const float* __restrict__ mask0, const float* __restrict__ depth1,
    const float* __restrict__ mask1, float* __restrict__ out)
{
    int tid = threadIdx.x;
    int blk = blockIdx.x;
    const int hw0 = 512 * 1024;

    if (blk >= 16384) {
        int idx = (blk - 16384) * 256 + tid;      // [0, 1048576)
        int x = idx & 511, y = (idx >> 9) & 255, b = idx >> 17;
        float rr[3];
        size_t rbase = (size_t)b * 3 * hw0 + (2 * y) * 1024 + 2 * x;
        #pragma unroll
        for (int c = 0; c < 3; c++) {
            float2 u0 = *(const float2*)(ref + rbase + (size_t)c * hw0);
            float2 u1 = *(const float2*)(ref + rbase + (size_t)c * hw0 + 1024);
            rr[c] = 0.25f * ((u0.x + u0.y) + (u1.x + u1.y));
        }
        float2 lc = g_lonT[1024 + x];
        float2 lt = g_latT[512 + y];
        float d = __ldg(depth1 + idx);
        float xx = d * lt.y * lc.x;
        float yy = d * lt.x;
        float zz = d * lt.y * lc.y;
        int p = y * 512 + x;
        float m0 = __ldg(mask1 + (size_t)(b * 2) * 131072 + p);
        float m1 = __ldg(mask1 + (size_t)(b * 2 + 1) * 131072 + p);
        float acc = dual_term(g_qm0, g_qm1, b, 256, 512, xx, yy, zz, rr[0], rr[1], rr[2], m0, m1);
        loss_reduce_finalize(acc, 1, out);
        return;
    }

    int lane = tid & 31, wid = tid >> 5;
    int bx = blk & 63;
    int by = (blk >> 6) & 31;
    int b  = blk >> 11;
    int tx = lane & 15;
    int sub = lane >> 4;
    int x = bx * 16 + tx;
    int y = by * 16 + wid * 2 + sub;

    int p = y * 1024 + x;
    size_t base3 = (size_t)b * 3 * hw0 + p;
    float r0 = __ldg(ref + base3), r1 = __ldg(ref + base3 + hw0), r2 = __ldg(ref + base3 + 2 * hw0);
    float d  = __ldg(depth0 + (size_t)b * hw0 + p);
    float m0 = __ldg(mask0 + (size_t)(b * 2) * hw0 + p);
    float m1 = __ldg(mask0 + (size_t)(b * 2 + 1) * hw0 + p);

    #define RED4(v) { v += __shfl_xor_sync(0xffffffffu, v, 1); v += __shfl_xor_sync(0xffffffffu, v, 16); v *= 0.25f; }
    float a0 = r0, a1 = r1, a2 = r2;
    RED4(a0); RED4(a1); RED4(a2);
    #undef RED4
    if (sub == 0 && (tx & 1) == 0) {
        int x2 = x >> 1, y2 = y >> 1;
        size_t ro = (size_t)(b * 3) * 131072 + y2 * 512 + x2;
        g_refM[ro] = a0; g_refM[ro + 131072] = a1; g_refM[ro + 262144] = a2;
    }

    float2 lc = g_lonT[x];
    float2 lt = g_latT[y];
    float xx = d * lt.y * lc.x;
    float yy = d * lt.x;
    float zz = d * lt.y * lc.y;
    float acc = dual_term(g_q0, g_q1, b, 512, 1024, xx, yy, zz, r0, r1, r2, m0, m1);
    loss_reduce_finalize(acc, 0, out);
}

// ---------- tail: loss levels 2..3 ----------
__global__ __launch_bounds__(256) void bp_loss23(
    const float* __restrict__ d2, const float* __restrict__ m2,
    const float* __restrict__ d3, const float* __restrict__ m3,
    float* __restrict__ out)
{
    int blk = blockIdx.x;
    const float *dep, *msk;
    int h, w, lw, lh, lonO, latO, accI, base, coff;
    if (blk < 1024) { dep = d2; msk = m2; h = 128; w = 256; lw = 8; lh = 7; lonO = 1536; latO = 768; coff = 1048576; accI = 2; base = 0; }
    else            { dep = d3; msk = m3; h = 64;  w = 128; lw = 7; lh = 6; lonO = 1792; latO = 896; coff = 1310720; accI = 3; base = 1024; }
    int idx = (blk - base) * 256 + threadIdx.x;
    int x = idx & (w - 1), y = (idx >> lw) & (h - 1), b = idx >> (lw + lh);

    float r0, r1, r2;
    {
        size_t pb = (size_t)(b * 3) * 131072;
        if (accI == 2) {
            size_t ro = pb + (2 * y) * 512 + 2 * x;
            float rr[3];
            #pragma unroll
            for (int c = 0; c < 3; c++) {
                float2 u0 = *(const float2*)(g_refM + ro + (size_t)c * 131072);
                float2 u1 = *(const float2*)(g_refM + ro + (size_t)c * 131072 + 512);
                rr[c] = 0.25f * ((u0.x + u0.y) + (u1.x + u1.y));
            }
            r0 = rr[0]; r1 = rr[1]; r2 = rr[2];
        } else {
            size_t ro = pb + (4 * y) * 512 + 4 * x;
            float rr[3];
            #pragma unroll
            for (int c = 0; c < 3; c++) {
                float s = 0.0f;
                #pragma unroll
                for (int rrow = 0; rrow < 4; rrow++) {
                    float4 u = *(const float4*)(g_refM + ro + (size_t)c * 131072 + rrow * 512);
                    s += u.x + u.y + u.z + u.w;
                }
                rr[c] = 0.0625f * s;
            }
            r0 = rr[0]; r1 = rr[1]; r2 = rr[2];
        }
    }

    float2 lc = g_lonT[lonO + x];
    float2 lt = g_latT[latO + y];
    float d = __ldg(dep + idx);
    float xx = d * lt.y * lc.x;
    float yy = d * lt.x;
    float zz = d * lt.y * lc.y;
    int hw = h * w;
    int p = y * w + x;
    float m0 = __ldg(msk + (size_t)(b * 2) * hw + p);
    float m1 = __ldg(msk + (size_t)(b * 2 + 1) * hw + p);
    float acc = dual_term_g(g_c0 + coff, g_c1 + coff, b, h, w, xx, yy, zz, r0, r1, r2, m0, m1);
    loss_reduce_finalize(acc, accI, out);
}

extern "C" void kernel_launch(void* const* d_in, const int* in_sizes, int n_in,
                              void* d_out, int out_size) {
    const float* depth[4];
    const float* mask[4];
    if (in_sizes[2] == 8388608) {
        for (int i = 0; i < 4; i++) {
            depth[i] = (const float*)d_in[1 + 2 * i];
            mask[i]  = (const float*)d_in[2 + 2 * i];
        }
    } else {
        for (int i = 0; i < 4; i++) {
            depth[i] = (const float*)d_in[1 + i];
            mask[i]  = (const float*)d_in[5 + i];
        }
    }
    const float* ref_rgb = (const float*)d_in[0];
    const float* tgt0 = (const float*)d_in[9];
    const float* tgt1 = (const float*)d_in[10];
    const float* pose = (const float*)d_in[11];
    float* out = (float*)d_out;

    bp_dense<<<4096, 256>>>(tgt0, tgt1, pose);
    bp_loss<<<16384 + 4096, 256>>>(ref_rgb, depth[0], mask[0], depth[1], mask[1], out);
    bp_loss23<<<1280, 256>>>(depth[2], mask[2], depth[3], mask[3], out);
    (void)n_in; (void)out_size;
}

// round 15
// speedup vs baseline: 1.0896x; 1.0419x over previous
#include <cuda_runtime.h>
#include <math.h>

#define PI_F 3.14159265358979323846f
#define HPI_F 1.57079632679489662f

#define BB 8

// ---------- static scratch ----------
__device__ uint4 g_q0[BB * 512 * 1024];   // L0 quads, channel-major
__device__ uint4 g_q1[BB * 512 * 1024];
// packed-RGB8 tgt mips per frame: L2@1048576 (32768/b), L3@1310720 (8192/b)
__device__ unsigned int g_c0[1376256];
__device__ unsigned int g_c1[1376256];
// channel-major quad mips for L1: 512x256 per b
__device__ uint4 g_qm0[1048576];
__device__ uint4 g_qm1[1048576];
__device__ float4 g_Rt[BB * 2 * 3];
__device__ float2 g_lonT[1920];
__device__ float2 g_latT[960];
__device__ double g_acc[4];
__device__ int g_done;

#define TOTAL_LOSS_BLOCKS (16384 + 4096 + 1024 + 256)

__device__ __forceinline__ float atanp(float r) {
    float z = r * r;
    float p = -0.0117212f;
    p = fmaf(p, z, 0.05265332f);
    p = fmaf(p, z, -0.11643287f);
    p = fmaf(p, z, 0.19354346f);
    p = fmaf(p, z, -0.33262347f);
    p = fmaf(p, z, 0.99997726f);
    return r * p;
}

__device__ __forceinline__ void project_eq(
    float px, float py, float pz, int h, int w, float& fx, float& fy)
{
    float ax = fabsf(px), az = fabsf(pz);
    float mn = fminf(ax, az), mx = fmaxf(ax, az);
    float t = atanp(__fdividef(mn, mx));
    t = (ax > az) ? (HPI_F - t) : t;
    t = (pz < 0.0f) ? (PI_F - t) : t;
    float lo = copysignf(t, px);
    float q = py * py;
    float s2 = fmaf(px, px, pz * pz);
    float mn2 = fminf(q, s2), mx2 = fmaxf(q, s2);
    float t2 = atanp(sqrtf(__fdividef(mn2, mx2)));
    t2 = (q > s2) ? (HPI_F - t2) : t2;
    float la = copysignf(t2, py);
    fx = (lo * (1.0f / PI_F) + 1.0f) * (0.5f * (float)(w - 1));
    fy = (la * (2.0f / PI_F) + 1.0f) * (0.5f * (float)(h - 1));
    fx = fminf(fmaxf(fx, 0.0f), (float)(w - 1));
    fy = fminf(fmaxf(fy, 0.0f), (float)(h - 1));
}

__device__ __forceinline__ unsigned int q8(float a, float b, float c) {
    unsigned int r = __float2uint_rn(__saturatef(a) * 255.0f);
    unsigned int g = __float2uint_rn(__saturatef(b) * 255.0f);
    unsigned int bl = __float2uint_rn(__saturatef(c) * 255.0f);
    return r | (g << 8) | (bl << 16);
}

__device__ __forceinline__ uint4 qassemble(unsigned a, unsigned b, unsigned c, unsigned d) {
    unsigned ab_r = __byte_perm(a, b, 0x0040), cd_r = __byte_perm(c, d, 0x0040);
    unsigned ab_g = __byte_perm(a, b, 0x0051), cd_g = __byte_perm(c, d, 0x0051);
    unsigned ab_b = __byte_perm(a, b, 0x0062), cd_b = __byte_perm(c, d, 0x0062);
    return make_uint4(__byte_perm(ab_r, cd_r, 0x5410),
                      __byte_perm(ab_g, cd_g, 0x5410),
                      __byte_perm(ab_b, cd_b, 0x5410), 0u);
}

__device__ __forceinline__ float quad_blend(
    uint4 Q, float fx, float fy, float r0, float r1, float r2, float m)
{
    float x0f = floorf(fx), y0f = floorf(fy);
    float wx1 = fx - x0f, wy1 = fy - y0f;
    float wx0 = 1.0f - wx1, wy0 = 1.0f - wy1;
    unsigned qa = __float2uint_rn(wx0 * wy0 * 255.0f);
    unsigned qc = __float2uint_rn(wx1 * wy0 * 255.0f);
    unsigned qb = __float2uint_rn(wx0 * wy1 * 255.0f);
    int qdi = 255 - (int)(qa + qc + qb);
    unsigned qd = (unsigned)max(qdi, 0);
    unsigned wq = qa | (qc << 8) | (qb << 16) | (qd << 24);
    const float inv = 1.0f / 65025.0f;
    float w0 = (float)__dp4a(Q.x, wq, 0u) * inv;
    float w1 = (float)__dp4a(Q.y, wq, 0u) * inv;
    float w2 = (float)__dp4a(Q.z, wq, 0u) * inv;
    return m * (fabsf(r0 - w0) + fabsf(r1 - w1) + fabsf(r2 - w2));
}

// dual-frame term: project both, load both, blend both (2x gather MLP)
__device__ __forceinline__ float dual_term(
    const uint4* __restrict__ Q0arr, const uint4* __restrict__ Q1arr,
    int b, int h, int w,
    float xx, float yy, float zz,
    float r0, float r1, float r2, float m0, float m1)
{
    const float4* Rt0 = g_Rt + (b * 2) * 3;
    float4 A0 = __ldg(Rt0), B0 = __ldg(Rt0 + 1), C0 = __ldg(Rt0 + 2);
    float4 A1 = __ldg(Rt0 + 3), B1 = __ldg(Rt0 + 4), C1 = __ldg(Rt0 + 5);
    float px0 = A0.x * xx + A0.y * yy + A0.z * zz + A0.w;
    float py0 = B0.x * xx + B0.y * yy + B0.z * zz + B0.w;
    float pz0 = C0.x * xx + C0.y * yy + C0.z * zz + C0.w;
    float px1 = A1.x * xx + A1.y * yy + A1.z * zz + A1.w;
    float py1 = B1.x * xx + B1.y * yy + B1.z * zz + B1.w;
    float pz1 = C1.x * xx + C1.y * yy + C1.z * zz + C1.w;
    float fx0, fy0, fx1, fy1;
    project_eq(px0, py0, pz0, h, w, fx0, fy0);
    project_eq(px1, py1, pz1, h, w, fx1, fy1);
    int x00 = (int)floorf(fx0), y00 = (int)floorf(fy0);
    int x01 = (int)floorf(fx1), y01 = (int)floorf(fy1);
    uint4 Q0 = __ldg(Q0arr + (size_t)(b * h + y00) * w + x00);
    uint4 Q1 = __ldg(Q1arr + (size_t)(b * h + y01) * w + x01);
    return quad_blend(Q0, fx0, fy0, r0, r1, r2, m0)
         + quad_blend(Q1, fx1, fy1, r0, r1, r2, m1);
}

// dual-frame term for small levels (assemble quads from RGB8 mip)
__device__ __forceinline__ float dual_term_g(
    const unsigned* __restrict__ C0arr, const unsigned* __restrict__ C1arr,
    int b, int h, int w,
    float xx, float yy, float zz,
    float r0, float r1, float r2, float m0, float m1)
{
    const float4* Rt0 = g_Rt + (b * 2) * 3;
    float4 A0 = __ldg(Rt0), B0 = __ldg(Rt0 + 1), C0 = __ldg(Rt0 + 2);
    float4 A1 = __ldg(Rt0 + 3), B1 = __ldg(Rt0 + 4), C1 = __ldg(Rt0 + 5);
    float px0 = A0.x * xx + A0.y * yy + A0.z * zz + A0.w;
    float py0 = B0.x * xx + B0.y * yy + B0.z * zz + B0.w;
    float pz0 = C0.x * xx + C0.y * yy + C0.z * zz + C0.w;
    float px1 = A1.x * xx + A1.y * yy + A1.z * zz + A1.w;
    float py1 = B1.x * xx + B1.y * yy + B1.z * zz + B1.w;
    float pz1 = C1.x * xx + C1.y * yy + C1.z * zz + C1.w;
    float fx0, fy0, fx1, fy1;
    project_eq(px0, py0, pz0, h, w, fx0, fy0);
    project_eq(px1, py1, pz1, h, w, fx1, fy1);
    int xa = (int)floorf(fx0), ya = (int)floorf(fy0);
    int xb = (int)floorf(fx1), yb = (int)floorf(fy1);
    int xa1 = min(xa + 1, w - 1), ya1 = min(ya + 1, h - 1);
    int xb1 = min(xb + 1, w - 1), yb1 = min(yb + 1, h - 1);
    const unsigned* b0 = C0arr + (size_t)b * h * w;
    const unsigned* b1 = C1arr + (size_t)b * h * w;
    unsigned c00a = __ldg(b0 + ya * w + xa),  c01a = __ldg(b0 + ya * w + xa1);
    unsigned c10a = __ldg(b0 + ya1 * w + xa), c11a = __ldg(b0 + ya1 * w + xa1);
    unsigned c00b = __ldg(b1 + yb * w + xb),  c01b = __ldg(b1 + yb * w + xb1);
    unsigned c10b = __ldg(b1 + yb1 * w + xb), c11b = __ldg(b1 + yb1 * w + xb1);
    uint4 Qa = qassemble(c00a, c01a, c10a, c11a);
    uint4 Qb = qassemble(c00b, c01b, c10b, c11b);
    return quad_blend(Qa, fx0, fy0, r0, r1, r2, m0)
         + quad_blend(Qb, fx1, fy1, r0, r1, r2, m1);
}

__device__ __forceinline__ void loss_reduce_finalize(float acc, int accIdx, float* out) {
    #pragma unroll
    for (int o = 16; o > 0; o >>= 1) acc += __shfl_down_sync(0xffffffffu, acc, o);
    __shared__ float ws[8];
    int lane = threadIdx.x & 31, warp = threadIdx.x >> 5;
    if (lane == 0) ws[warp] = acc;
    __syncthreads();
    if (threadIdx.x == 0) {
        float s = 0.0f;
        #pragma unroll
        for (int i = 0; i < 8; i++) s += ws[i];
        atomicAdd(&g_acc[accIdx], (double)s);
        __threadfence();
        int done = atomicAdd(&g_done, 1);
        if (done == TOTAL_LOSS_BLOCKS - 1) {
            double l = g_acc[0] * (1.0 / 12582912.0)
                     + g_acc[1] * (1.0 / 3145728.0)
                     + g_acc[2] * (1.0 / 786432.0)
                     + g_acc[3] * (1.0 / 196608.0);
            out[0] = (float)l;
        }
    }
}

// ---------- DENSE: 32x32 tile; L0 quads, L1 quad mips, L2/L3 RGB8 mips ----------
__global__ __launch_bounds__(256) void bp_dense(
    const float* __restrict__ tgt0, const float* __restrict__ tgt1,
    const float* __restrict__ pose)
{
    int tid = threadIdx.x;
    int blk = blockIdx.x;            // 4096 = 32 x 16 x 8

    if (blk == 0) {
        if (tid < 4) g_acc[tid] = 0.0;
        if (tid == 4) g_done = 0;
        if (tid < BB * 2) {
            const float* p = pose + tid * 6;
            float rx = p[3], ry = p[4], rz = p[5];
            float th = sqrtf(rx * rx + ry * ry + rz * rz);
            float inv = 1.0f / fmaxf(th, 1e-8f);
            float kx = rx * inv, ky = ry * inv, kz = rz * inv;
            float s = sinf(th), c = cosf(th), ic = 1.0f - c;
            g_Rt[tid * 3 + 0] = make_float4(c + ic * kx * kx,      ic * kx * ky - s * kz, ic * kx * kz + s * ky, p[0]);
            g_Rt[tid * 3 + 1] = make_float4(ic * ky * kx + s * kz, c + ic * ky * ky,      ic * ky * kz - s * kx, p[1]);
            g_Rt[tid * 3 + 2] = make_float4(ic * kz * kx - s * ky, ic * kz * ky + s * kx, c + ic * kz * kz,      p[2]);
        }
        for (int i = tid; i < 1920; i += 256) {
            int off, w;
            if (i < 1024)      { off = 0;    w = 1024; }
            else if (i < 1536) { off = 1024; w = 512; }
            else if (i < 1792) { off = 1536; w = 256; }
            else               { off = 1792; w = 128; }
            int xi = i - off;
            float lon = ((xi + 0.5f) / (float)w * 2.0f - 1.0f) * PI_F;
            g_lonT[i] = make_float2(sinf(lon), cosf(lon));
        }
        for (int i = tid; i < 960; i += 256) {
            int off, h;
            if (i < 512)      { off = 0;   h = 512; }
            else if (i < 768) { off = 512; h = 256; }
            else if (i < 896) { off = 768; h = 128; }
            else              { off = 896; h = 64; }
            int yi = i - off;
            float lat = -((yi + 0.5f) / (float)h * 2.0f - 1.0f) * HPI_F;
            g_latT[i] = make_float2(sinf(lat), cosf(lat));
        }
    }

    int bx = blk & 31;
    int by = (blk >> 5) & 15;
    int b  = blk >> 9;
    int sx = tid & 7;
    int sy = tid >> 3;
    int x0 = bx * 32 + sx * 4;
    int y  = by * 32 + sy;

    const int hw = 512 * 1024;
    size_t base3 = (size_t)b * 3 * hw + y * 1024 + x0;

    float4 a0 = *(const float4*)(tgt0 + base3);
    float4 a1 = *(const float4*)(tgt0 + base3 + hw);
    float4 a2 = *(const float4*)(tgt0 + base3 + 2 * hw);
    float4 b0 = *(const float4*)(tgt1 + base3);
    float4 b1 = *(const float4*)(tgt1 + base3 + hw);
    float4 b2 = *(const float4*)(tgt1 + base3 + 2 * hw);

    unsigned wA0 = q8(a0.x, a1.x, a2.x), wA1 = q8(a0.y, a1.y, a2.y);
    unsigned wA2 = q8(a0.z, a1.z, a2.z), wA3 = q8(a0.w, a1.w, a2.w);
    unsigned wB0 = q8(b0.x, b1.x, b2.x), wB1 = q8(b0.y, b1.y, b2.y);
    unsigned wB2 = q8(b0.z, b1.z, b2.z), wB3 = q8(b0.w, b1.w, b2.w);

    __shared__ unsigned smA[34 * 34], smB[34 * 34];
    {
        int si = sy * 34 + sx * 4;
        smA[si + 0] = wA0; smA[si + 1] = wA1; smA[si + 2] = wA2; smA[si + 3] = wA3;
        smB[si + 0] = wB0; smB[si + 1] = wB1; smB[si + 2] = wB2; smB[si + 3] = wB3;
    }
    for (int i = tid; i < 264; i += 256) {
        int f = (i >= 132);
        int j = i - f * 132;
        int lxh, lyh;
        if (j < 68) { lxh = 32 + (j & 1); lyh = j >> 1; }
        else        { int k = j - 68; lyh = 32 + (k & 1); lxh = k >> 1; }
        int gx = min(bx * 32 + lxh, 1023);
        int gy = min(by * 32 + lyh, 511);
        const float* src = f ? tgt1 : tgt0;
        size_t hb = (size_t)b * 3 * hw + gy * 1024 + gx;
        unsigned v = q8(__ldg(src + hb), __ldg(src + hb + hw), __ldg(src + hb + 2 * hw));
        (f ? smB : smA)[lyh * 34 + lxh] = v;
    }

    float h0A0 = a0.x + a0.y, h1A0 = a0.z + a0.w;
    float h0A1 = a1.x + a1.y, h1A1 = a1.z + a1.w;
    float h0A2 = a2.x + a2.y, h1A2 = a2.z + a2.w;
    float h0B0 = b0.x + b0.y, h1B0 = b0.z + b0.w;
    float h0B1 = b1.x + b1.y, h1B1 = b1.z + b1.w;
    float h0B2 = b2.x + b2.y, h1B2 = b2.z + b2.w;
    #define Vred(v) v += __shfl_xor_sync(0xffffffffu, v, 8); v *= 0.25f;
    Vred(h0A0); Vred(h1A0); Vred(h0A1); Vred(h1A1); Vred(h0A2); Vred(h1A2);
    Vred(h0B0); Vred(h1B0); Vred(h0B1); Vred(h1B1); Vred(h0B2); Vred(h1B2);
    #undef Vred

    __shared__ float4 st0[256];
    __shared__ float4 st1[256];
    __shared__ float4 st0b[64];
    __shared__ float4 st1b[64];
    __shared__ unsigned smQ0[17 * 17], smQ1[17 * 17];

    if ((sy & 1) == 0) {
        int lx1 = sx * 2, ly1 = sy >> 1;
        int si = ly1 * 16 + lx1;
        st0[si]     = make_float4(h0A0, h0A1, h0A2, 0.0f);
        st0[si + 1] = make_float4(h1A0, h1A1, h1A2, 0.0f);
        st1[si]     = make_float4(h0B0, h0B1, h0B2, 0.0f);
        st1[si + 1] = make_float4(h1B0, h1B1, h1B2, 0.0f);
        int qi = ly1 * 17 + lx1;
        smQ0[qi]     = q8(h0A0, h0A1, h0A2);
        smQ0[qi + 1] = q8(h1A0, h1A1, h1A2);
        smQ1[qi]     = q8(h0B0, h0B1, h0B2);
        smQ1[qi + 1] = q8(h1B0, h1B1, h1B2);
    }
    __syncthreads();

    // ---- L0 quad assembly: own words from registers, neighbor + next row from smem ----
    {
        int si = sy * 34 + sx * 4;
        unsigned rA0[5] = {wA0, wA1, wA2, wA3, smA[si + 4]};
        unsigned rB0[5] = {wB0, wB1, wB2, wB3, smB[si + 4]};
        unsigned rA1[5], rB1[5];
        #pragma unroll
        for (int i = 0; i < 5; i++) {
            rA1[i] = smA[si + 34 + i];
            rB1[i] = smB[si + 34 + i];
        }
        size_t go = (size_t)(b * 512 + y) * 1024 + x0;
        #pragma unroll
        for (int i = 0; i < 4; i++) {
            g_q0[go + i] = qassemble(rA0[i], rA0[i + 1], rA1[i], rA1[i + 1]);
            g_q1[go + i] = qassemble(rB0[i], rB0[i + 1], rB1[i], rB1[i + 1]);
        }
    }

    // ---- L1 u8 halo (17th row/col), clamped at L1 coords ----
    if (tid < 66) {
        int f = (tid >= 33);
        int j = tid - f * 33;
        int lx1, ly1;
        if (j < 17) { lx1 = 16; ly1 = j; }
        else        { ly1 = 16; lx1 = j - 17; }
        int gx2 = min(bx * 16 + lx1, 511);
        int gy2 = min(by * 16 + ly1, 255);
        int l0x = 2 * gx2 - bx * 32;
        int l0y = 2 * gy2 - by * 32;
        const unsigned* S = f ? smB : smA;
        unsigned w00 = S[l0y * 34 + l0x],       w01 = S[l0y * 34 + l0x + 1];
        unsigned w10 = S[(l0y + 1) * 34 + l0x], w11 = S[(l0y + 1) * 34 + l0x + 1];
        unsigned mword = 0;
        #pragma unroll
        for (int c = 0; c < 24; c += 8) {
            unsigned s = ((w00 >> c) & 255u) + ((w01 >> c) & 255u)
                       + ((w10 >> c) & 255u) + ((w11 >> c) & 255u);
            mword |= (((s + 2u) >> 2) & 255u) << c;
        }
        (f ? smQ1 : smQ0)[ly1 * 17 + lx1] = mword;
    }

    // ---- L2 (8x8 per block) ----
    if (tid < 64) {
        int lx2 = tid & 7, ly2 = tid >> 3;
        int i00 = (2 * ly2) * 16 + 2 * lx2;
        int i01 = i00 + 1, i10 = i00 + 16, i11 = i00 + 17;
        float q0x = 0.25f * (st0[i00].x + st0[i01].x + st0[i10].x + st0[i11].x);
        float q0y = 0.25f * (st0[i00].y + st0[i01].y + st0[i10].y + st0[i11].y);
        float q0z = 0.25f * (st0[i00].z + st0[i01].z + st0[i10].z + st0[i11].z);
        float q1x = 0.25f * (st1[i00].x + st1[i01].x + st1[i10].x + st1[i11].x);
        float q1y = 0.25f * (st1[i00].y + st1[i01].y + st1[i10].y + st1[i11].y);
        float q1z = 0.25f * (st1[i00].z + st1[i01].z + st1[i10].z + st1[i11].z);
        int x2g = bx * 8 + lx2, y2g = by * 8 + ly2;
        g_c0[1048576 + (b * 128 + y2g) * 256 + x2g] = q8(q0x, q0y, q0z);
        g_c1[1048576 + (b * 128 + y2g) * 256 + x2g] = q8(q1x, q1y, q1z);
        int si = ly2 * 8 + lx2;
        st0b[si] = make_float4(q0x, q0y, q0z, 0.0f);
        st1b[si] = make_float4(q1x, q1y, q1z, 0.0f);
    }
    __syncthreads();

    // ---- L1 quad-mip assembly ----
    {
        int lx = tid & 15, ly = tid >> 4;
        int qi = ly * 17 + lx;
        int x2g = bx * 16 + lx, y2g = by * 16 + ly;
        size_t go = (size_t)(b * 256 + y2g) * 512 + x2g;
        g_qm0[go] = qassemble(smQ0[qi], smQ0[qi + 1], smQ0[qi + 17], smQ0[qi + 18]);
        g_qm1[go] = qassemble(smQ1[qi], smQ1[qi + 1], smQ1[qi + 17], smQ1[qi + 18]);
    }

    // ---- L3 (4x4 per block) ----
    if (tid < 16) {
        int lx3 = tid & 3, ly3 = tid >> 2;
        int i00 = (2 * ly3) * 8 + 2 * lx3;
        int i01 = i00 + 1, i10 = i00 + 8, i11 = i00 + 9;
        float q0x = 0.25f * (st0b[i00].x + st0b[i01].x + st0b[i10].x + st0b[i11].x);
        float q0y = 0.25f * (st0b[i00].y + st0b[i01].y + st0b[i10].y + st0b[i11].y);
        float q0z = 0.25f * (st0b[i00].z + st0b[i01].z + st0b[i10].z + st0b[i11].z);
        float q1x = 0.25f * (st1b[i00].x + st1b[i01].x + st1b[i10].x + st1b[i11].x);
        float q1y = 0.25f * (st1b[i00].y + st1b[i01].y + st1b[i10].y + st1b[i11].y);
        float q1z = 0.25f * (st1b[i00].z + st1b[i01].z + st1b[i10].z + st1b[i11].z);
        int x3g = bx * 4 + lx3, y3g = by * 4 + ly3;
        g_c0[1310720 + (b * 64 + y3g) * 128 + x3g] = q8(q0x, q0y, q0z);
        g_c1[1310720 + (b * 64 + y3g) * 128 + x3g] = q8(q1x, q1y, q1z);
    }
}

// ---------- single merged loss kernel: all 4 levels by block range ----------
__global__ __launch_bounds__(256) void bp_loss(
    const float* __restrict__ ref, const float* __restrict__ depth0,
    const float* __restrict__ mask0, const float* __restrict__ depth1,
    const float* __restrict__ mask1, const float* __restrict__ depth2,
    const float* __restrict__ mask2, const float* __restrict__ depth3,
    const float* __restrict__ mask3, float* __restrict__ out)
{
    int tid = threadIdx.x;
    int blk = blockIdx.x;
    const int hw0 = 512 * 1024;

    if (blk < 16384) {
        // ---- level 0 ----
        int lane = tid & 31, wid = tid >> 5;
        int bx = blk & 63, by = (blk >> 6) & 31, b = blk >> 11;
        int x = bx * 16 + (lane & 15);
        int y = by * 16 + wid * 2 + (lane >> 4);
        int p = y * 1024 + x;
        size_t base3 = (size_t)b * 3 * hw0 + p;
        float r0 = __ldg(ref + base3), r1 = __ldg(ref + base3 + hw0), r2 = __ldg(ref + base3 + 2 * hw0);
        float d  = __ldg(depth0 + (size_t)b * hw0 + p);
        float m0 = __ldg(mask0 + (size_t)(b * 2) * hw0 + p);
        float m1 = __ldg(mask0 + (size_t)(b * 2 + 1) * hw0 + p);
        float2 lc = g_lonT[x];
        float2 lt = g_latT[y];
        float xx = d * lt.y * lc.x;
        float yy = d * lt.x;
        float zz = d * lt.y * lc.y;
        float acc = dual_term(g_q0, g_q1, b, 512, 1024, xx, yy, zz, r0, r1, r2, m0, m1);
        loss_reduce_finalize(acc, 0, out);
    } else if (blk < 20480) {
        // ---- level 1 ----
        int idx = (blk - 16384) * 256 + tid;
        int x = idx & 511, y = (idx >> 9) & 255, b = idx >> 17;
        float rr[3];
        size_t rbase = (size_t)b * 3 * hw0 + (2 * y) * 1024 + 2 * x;
        #pragma unroll
        for (int c = 0; c < 3; c++) {
            float2 u0 = *(const float2*)(ref + rbase + (size_t)c * hw0);
            float2 u1 = *(const float2*)(ref + rbase + (size_t)c * hw0 + 1024);
            rr[c] = 0.25f * ((u0.x + u0.y) + (u1.x + u1.y));
        }
        float2 lc = g_lonT[1024 + x];
        float2 lt = g_latT[512 + y];
        float d = __ldg(depth1 + idx);
        float xx = d * lt.y * lc.x;
        float yy = d * lt.x;
        float zz = d * lt.y * lc.y;
        int p = y * 512 + x;
        float m0 = __ldg(mask1 + (size_t)(b * 2) * 131072 + p);
        float m1 = __ldg(mask1 + (size_t)(b * 2 + 1) * 131072 + p);
        float acc = dual_term(g_qm0, g_qm1, b, 256, 512, xx, yy, zz, rr[0], rr[1], rr[2], m0, m1);
        loss_reduce_finalize(acc, 1, out);
    } else if (blk < 21504) {
        // ---- level 2: ref = mean of 4x4 L0 block ----
        int idx = (blk - 20480) * 256 + tid;      // [0, 262144)
        int x = idx & 255, y = (idx >> 8) & 127, b = idx >> 15;
        float rr[3];
        size_t rbase = (size_t)b * 3 * hw0 + (4 * y) * 1024 + 4 * x;
        #pragma unroll
        for (int c = 0; c < 3; c++) {
            float s = 0.0f;
            #pragma unroll
            for (int r = 0; r < 4; r++) {
                float4 u = *(const float4*)(ref + rbase + (size_t)c * hw0 + r * 1024);
                s += (u.x + u.y) + (u.z + u.w);
            }
            rr[c] = 0.0625f * s;
        }
        float2 lc = g_lonT[1536 + x];
        float2 lt = g_latT[768 + y];
        float d = __ldg(depth2 + idx);
        float xx = d * lt.y * lc.x;
        float yy = d * lt.x;
        float zz = d * lt.y * lc.y;
        int p = y * 256 + x;
        float m0 = __ldg(mask2 + (size_t)(b * 2) * 32768 + p);
        float m1 = __ldg(mask2 + (size_t)(b * 2 + 1) * 32768 + p);
        float acc = dual_term_g(g_c0 + 1048576, g_c1 + 1048576, b, 128, 256,
                                xx, yy, zz, rr[0], rr[1], rr[2], m0, m1);
        loss_reduce_finalize(acc, 2, out);
    } else {
        // ---- level 3: ref = mean of 8x8 L0 block ----
        int idx = (blk - 21504) * 256 + tid;      // [0, 65536)
        int x = idx & 127, y = (idx >> 7) & 63, b = idx >> 13;
        float rr[3];
        size_t rbase = (size_t)b * 3 * hw0 + (8 * y) * 1024 + 8 * x;
        #pragma unroll
        for (int c = 0; c < 3; c++) {
            float s = 0.0f;
            #pragma unroll
            for (int r = 0; r < 8; r++) {
                float4 u0 = *(const float4*)(ref + rbase + (size_t)c * hw0 + r * 1024);
                float4 u1 = *(const float4*)(ref + rbase + (size_t)c * hw0 + r * 1024 + 4);
                s += (u0.x + u0.y) + (u0.z + u0.w) + (u1.x + u1.y) + (u1.z + u1.w);
            }
            rr[c] = 0.015625f * s;
        }
        float2 lc = g_lonT[1792 + x];
        float2 lt = g_latT[896 + y];
        float d = __ldg(depth3 + idx);
        float xx = d * lt.y * lc.x;
        float yy = d * lt.x;
        float zz = d * lt.y * lc.y;
        int p = y * 128 + x;
        float m0 = __ldg(mask3 + (size_t)(b * 2) * 8192 + p);
        float m1 = __ldg(mask3 + (size_t)(b * 2 + 1) * 8192 + p);
        float acc = dual_term_g(g_c0 + 1310720, g_c1 + 1310720, b, 64, 128,
                                xx, yy, zz, rr[0], rr[1], rr[2], m0, m1);
        loss_reduce_finalize(acc, 3, out);
    }
}

extern "C" void kernel_launch(void* const* d_in, const int* in_sizes, int n_in,
                              void* d_out, int out_size) {
    const float* depth[4];
    const float* mask[4];
    if (in_sizes[2] == 8388608) {
        for (int i = 0; i < 4; i++) {
            depth[i] = (const float*)d_in[1 + 2 * i];
            mask[i]  = (const float*)d_in[2 + 2 * i];
        }
    } else {
        for (int i = 0; i < 4; i++) {
            depth[i] = (const float*)d_in[1 + i];
            mask[i]  = (const float*)d_in[5 + i];
        }
    }
    const float* ref_rgb = (const float*)d_in[0];
    const float* tgt0 = (const float*)d_in[9];
    const float* tgt1 = (const float*)d_in[10];
    const float* pose = (const float*)d_in[11];
    float* out = (float*)d_out;

    bp_dense<<<4096, 256>>>(tgt0, tgt1, pose);
    bp_loss<<<TOTAL_LOSS_BLOCKS, 256>>>(ref_rgb, depth[0], mask[0], depth[1], mask[1],
                                        depth[2], mask[2], depth[3], mask[3], out);
    (void)n_in; (void)out_size;
}